// round 12
// baseline (speedup 1.0000x reference)
#include <cuda_runtime.h>
#include <cstdint>

// out[b, l] = x[b, perm[b, l]]   (B=1024, L=16384)
// Split=2 (two CTAs per row, grid=2048) at 1024 threads, 2 CTAs/SM = 100%
// thread occupancy. Each CTA TMA-loads the FULL row (pair's duplicate read
// dedups in L2), gathers/stores only its half (2 int4 + 2 float4 per thread).
// Combines R8's finer wave granularity with R11's full occupancy.

#define THREADS 1024

__global__ __launch_bounds__(THREADS, 2)
void interleave_h1024_kernel(const float* __restrict__ x,
                             const int* __restrict__ perm,
                             float* __restrict__ out,
                             int L) {
    extern __shared__ __align__(128) unsigned char smem_raw[];
    float* srow = reinterpret_cast<float*>(smem_raw);
    uint64_t* mbar_p = reinterpret_cast<uint64_t*>(smem_raw + (size_t)L * sizeof(float));
    uint32_t mbar = (uint32_t)__cvta_generic_to_shared(mbar_p);
    uint32_t sdst = (uint32_t)__cvta_generic_to_shared(srow);

    long long row = blockIdx.x >> 1;
    int half = blockIdx.x & 1;
    int H = L >> 1;                        // 8192 elements per half
    long long base = row * (long long)L + (long long)half * H;

    const float* xrow  = x + row * (long long)L;
    const int*   phalf = perm + base;
    float*       ohalf = out + base;

    int tid = threadIdx.x;
    unsigned bytes = (unsigned)L * 4u;

    if (tid == 0) {
        asm volatile("mbarrier.init.shared.b64 [%0], %1;"
                     :: "r"(mbar), "r"(1) : "memory");
    }
    __syncthreads();

    if (tid == 0) {
        asm volatile("mbarrier.arrive.expect_tx.shared.b64 _, [%0], %1;"
                     :: "r"(mbar), "r"(bytes) : "memory");
        asm volatile("cp.async.bulk.shared::cta.global.mbarrier::complete_tx::bytes "
                     "[%0], [%1], %2, [%3];"
                     :: "r"(sdst), "l"(xrow), "r"(bytes), "r"(mbar) : "memory");
    }

    // Prefetch this half's perm while the TMA streams the row.
    // H/4 = 2048 int4 = 2 * THREADS exactly.
    const int4* p4 = reinterpret_cast<const int4*>(phalf);
    int4 p0 = __ldcs(p4 + tid);
    int4 p1 = __ldcs(p4 + tid + THREADS);

    // Wait for the row (acquire orders subsequent smem reads).
    {
        uint32_t done;
        asm volatile(
            "{\n\t.reg .pred P;\n\t"
            "mbarrier.try_wait.parity.acquire.cta.shared::cta.b64 P, [%1], %2;\n\t"
            "selp.b32 %0, 1, 0, P;\n\t}"
            : "=r"(done) : "r"(mbar), "r"(0u) : "memory");
        if (!done) {
            asm volatile(
                "{\n\t.reg .pred P;\n\t"
                "W_%=:\n\t"
                "mbarrier.try_wait.parity.acquire.cta.shared::cta.b64 P, [%0], %1, 0x989680;\n\t"
                "@P bra.uni D_%=;\n\t"
                "bra.uni W_%=;\n\t"
                "D_%=:\n\t}"
                :: "r"(mbar), "r"(0u) : "memory");
        }
    }

    // Gather from SMEM, coalesced streaming stores.
    float4* o4 = reinterpret_cast<float4*>(ohalf);
    float4 o;
    o.x = srow[p0.x]; o.y = srow[p0.y]; o.z = srow[p0.z]; o.w = srow[p0.w];
    __stcs(o4 + tid, o);
    o.x = srow[p1.x]; o.y = srow[p1.y]; o.z = srow[p1.z]; o.w = srow[p1.w];
    __stcs(o4 + tid + THREADS, o);
}

extern "C" void kernel_launch(void* const* d_in, const int* in_sizes, int n_in,
                              void* d_out, int out_size) {
    const float* x   = (const float*)d_in[0];
    const int* perm  = (const int*)d_in[1];
    float* out       = (float*)d_out;

    long long total = (long long)in_sizes[1];
    int B = 1024;
    int L = (int)(total / B);

    size_t smem = (size_t)L * sizeof(float) + 16;
    cudaFuncSetAttribute(interleave_h1024_kernel,
                         cudaFuncAttributeMaxDynamicSharedMemorySize, (int)smem);

    interleave_h1024_kernel<<<2 * B, THREADS, smem>>>(x, perm, out, L);
}